// round 7
// baseline (speedup 1.0000x reference)
#include <cuda_runtime.h>
#include <cstdint>

#define T_SEQ 32768
#define HID   512
#define CS    16       // cluster size per direction (nonportable, 2 clusters)
#define NTHR  256      // threads per scan CTA

// 64 MB scratch for xp = x @ Wx^T + b  (device global: allowed, no runtime alloc)
__device__ float g_xp[(size_t)T_SEQ * HID];

// ---------------------------------------------------------------------------
// Kernel 1: xp[m,n] = sum_k x[m,k] * Wx[n,k] + b[n]   (unchanged)
// ---------------------------------------------------------------------------
#define BM 128
#define BN 128
#define BK 16

__global__ void __launch_bounds__(256) gemm_xp_kernel(
    const float* __restrict__ x, const float* __restrict__ Wx,
    const float* __restrict__ b)
{
    __shared__ float As[BK][BM + 4];
    __shared__ float Bs[BK][BN + 4];
    const int bm  = blockIdx.y * BM;
    const int bn  = blockIdx.x * BN;
    const int tid = threadIdx.x;
    const int tx  = tid & 15;
    const int ty  = tid >> 4;

    float acc[8][8];
#pragma unroll
    for (int i = 0; i < 8; i++)
#pragma unroll
        for (int j = 0; j < 8; j++) acc[i][j] = 0.f;

    for (int k0 = 0; k0 < HID; k0 += BK) {
#pragma unroll
        for (int i = 0; i < 2; i++) {
            int idx = tid * 2 + i;
            int r   = idx >> 2;
            int c4  = (idx & 3) * 4;
            float4 va = *(const float4*)&x [(size_t)(bm + r) * HID + k0 + c4];
            As[c4 + 0][r] = va.x; As[c4 + 1][r] = va.y;
            As[c4 + 2][r] = va.z; As[c4 + 3][r] = va.w;
            float4 vb = *(const float4*)&Wx[(size_t)(bn + r) * HID + k0 + c4];
            Bs[c4 + 0][r] = vb.x; Bs[c4 + 1][r] = vb.y;
            Bs[c4 + 2][r] = vb.z; Bs[c4 + 3][r] = vb.w;
        }
        __syncthreads();
#pragma unroll
        for (int k = 0; k < BK; k++) {
            float a[8], bb[8];
#pragma unroll
            for (int i = 0; i < 8; i++) a[i]  = As[k][ty * 8 + i];
#pragma unroll
            for (int j = 0; j < 8; j++) bb[j] = Bs[k][tx * 8 + j];
#pragma unroll
            for (int i = 0; i < 8; i++)
#pragma unroll
                for (int j = 0; j < 8; j++)
                    acc[i][j] = fmaf(a[i], bb[j], acc[i][j]);
        }
        __syncthreads();
    }

#pragma unroll
    for (int i = 0; i < 8; i++) {
        int m = bm + ty * 8 + i;
#pragma unroll
        for (int j = 0; j < 8; j += 4) {
            int n = bn + tx * 8 + j;
            float4 v;
            v.x = acc[i][j + 0] + b[n + 0];
            v.y = acc[i][j + 1] + b[n + 1];
            v.z = acc[i][j + 2] + b[n + 2];
            v.w = acc[i][j + 3] + b[n + 3];
            *(float4*)&g_xp[(size_t)m * HID + n] = v;
        }
    }
}

// ---------------------------------------------------------------------------
// Kernel 2: recurrent scans. 2 clusters x 16 CTAs x 256 threads.
// R7 layout: group g = tid>>4 owns rows {rk*32+2g, rk*32+2g+1}; lane l = tid&15
// owns 32 cols. Swizzle-packed weights make each fma.rn.f32x2 accumulate BOTH
// rows at once, so after a 4-level butterfly every lane holds (h_r0, h_r1)
// packed -> one st.async.b64 per thread to rank l. 256 msgs/CTA/step (half of
// R5/R6), expect_tx unchanged at 2048 B.
// ---------------------------------------------------------------------------
__device__ __forceinline__ uint32_t smem_u32(const void* p) {
    uint32_t a;
    asm("{ .reg .u64 t; cvta.to.shared.u64 t, %1; cvt.u32.u64 %0, t; }"
        : "=r"(a) : "l"(p));
    return a;
}

#define MBAR_INIT(addr, cnt) \
    asm volatile("mbarrier.init.shared.b64 [%0], %1;" :: "r"(addr), "r"(cnt) : "memory")

#define MBAR_ARRIVE_EXPECT_TX(addr, tx) \
    asm volatile("mbarrier.arrive.expect_tx.shared.b64 _, [%0], %1;" \
                 :: "r"(addr), "r"(tx) : "memory")

#define MBAR_WAIT(addr, ph) do {                                               \
    uint32_t _done;                                                            \
    asm volatile("{\n\t.reg .pred p;\n\t"                                      \
        "mbarrier.try_wait.parity.acquire.cta.shared::cta.b64 p, [%1], %2;\n\t"\
        "selp.b32 %0, 1, 0, p;\n\t}"                                           \
        : "=r"(_done) : "r"(addr), "r"(ph) : "memory");                        \
    if (!_done) {                                                              \
        asm volatile("{\n\t.reg .pred P1;\n\t"                                 \
            "WL_%=:\n\t"                                                       \
            "mbarrier.try_wait.parity.acquire.cta.shared::cta.b64 P1, [%0], %1, 0x989680;\n\t" \
            "@P1 bra.uni WD_%=;\n\t"                                           \
            "bra.uni WL_%=;\n\t"                                               \
            "WD_%=:\n\t}"                                                      \
            :: "r"(addr), "r"(ph) : "memory");                                 \
    }                                                                          \
} while (0)

#define HPAD 544   // 8 chunks * 68 words: word = col + 4*(col/64), conflict-free

__global__ void __launch_bounds__(NTHR, 1)
scan_kernel(const float* __restrict__ Wh, float* __restrict__ out)
{
    __shared__ alignas(16) float hs[2][HPAD];
    __shared__ alignas(8) unsigned long long mbar[2];

    const int tid = threadIdx.x;
    const int dir = blockIdx.x / CS;     // 0 = forward, 1 = reverse
    const int rk  = blockIdx.x % CS;     // cluster rank
    const int g   = tid >> 4;            // 0..15 row-pair group
    const int l   = tid & 15;            // 0..15 col chunk + send target rank
    const int r0  = rk * 32 + 2 * g;     // first of my two global rows

    // ---- swizzle-packed weights: 32 cols for rows r0 and r0+1 ----
    // wP[j] = (Wh[r0][2j], Wh[r1][2j+1]);  wQ[j] = (Wh[r1][2j], Wh[r0][2j+1])
    unsigned long long wP[16], wQ[16];
    {
        const float* w0 = &Wh[(size_t)r0 * HID + l * 32];
        const float* w1 = &Wh[(size_t)(r0 + 1) * HID + l * 32];
#pragma unroll
        for (int j = 0; j < 16; j++) {
            float2 a = *(const float2*)&w0[2 * j];
            float2 b = *(const float2*)&w1[2 * j];
            asm("mov.b64 %0, {%1,%2};" : "=l"(wP[j]) : "f"(a.x), "f"(b.y));
            asm("mov.b64 %0, {%1,%2};" : "=l"(wQ[j]) : "f"(b.x), "f"(a.y));
        }
    }

    // ---- zero both h buffers (h0 = 0) ----
    for (int i = tid; i < 2 * HPAD; i += NTHR) ((float*)hs)[i] = 0.f;

    const uint32_t buf0  = smem_u32(&hs[0][0]);
    const uint32_t mb    = smem_u32(&mbar[0]);
    const uint32_t mbrel = mb - buf0;    // mbar offset relative to hs base

    // my single send target: rank l (DSMEM addressing linear in local offset)
    uint32_t myrb;
    asm("mapa.shared::cluster.u32 %0, %1, %2;"
        : "=r"(myrb) : "r"(buf0), "r"(l));

    if (tid == 0) {
        MBAR_INIT(mb,     1u);
        MBAR_INIT(mb + 8, 1u);
        // pre-arm both phases: 256 msgs x 8B = 2048 B
        MBAR_ARRIVE_EXPECT_TX(mb,     2048u);
        MBAR_ARRIVE_EXPECT_TX(mb + 8, 2048u);
    }
    __syncthreads();
    // all CTAs: buffers zeroed + mbars armed before any remote st.async
    asm volatile("barrier.cluster.arrive.aligned;" ::: "memory");
    asm volatile("barrier.cluster.wait.aligned;"   ::: "memory");

    float* out_h = out + 512 + (size_t)dir * T_SEQ * HID;

    // my h-pair's destination word in every CTA's buffer:
    // col = rk*32 + 2g -> word 68*(rk>>1) + 32*(rk&1) + 2g  (8B-aligned: all even)
    const uint32_t doff0 =
        (uint32_t)(68 * (rk >> 1) + 32 * (rk & 1) + 2 * g) * 4u;
    const uint32_t doff1 = doff0 + (uint32_t)HPAD * 4u;

    // my h-read base: cols l*32..l*32+31 -> word 68*(l>>1) + 32*(l&1)
    const int hbase = 68 * (l >> 1) + 32 * (l & 1);

    // ---- xp software pipeline (depth 2): float2 covering rows r0, r0+1 ----
    float2 xp0, xp1;
    {
        size_t i0 = (size_t)(dir ? (T_SEQ - 1) : 0) * HID + r0;
        size_t i1 = (size_t)(dir ? (T_SEQ - 2) : 1) * HID + r0;
        xp0 = *(const float2*)&g_xp[i0];
        xp1 = *(const float2*)&g_xp[i1];
    }

    int ph0 = 0, ph1 = 0;

    for (int t = 0; t < T_SEQ; t++) {
        float2 xpn = make_float2(0.f, 0.f);
        if (t + 2 < T_SEQ) {
            size_t ii = (size_t)(dir ? (T_SEQ - 3 - t) : (t + 2)) * HID + r0;
            xpn = *(const float2*)&g_xp[ii];
        }

        const int cur = t & 1;
        if (t > 0) {
            if (cur) {
                MBAR_WAIT(mb + 8, ph1); ph1 ^= 1;
                // re-arm for phase t+2; early peer tx absorbed (count may go
                // transiently negative)
                if (tid == 0 && t + 2 < T_SEQ)
                    MBAR_ARRIVE_EXPECT_TX(mb + 8, 2048u);
            } else {
                MBAR_WAIT(mb, ph0); ph0 ^= 1;
                if (tid == 0 && t + 2 < T_SEQ)
                    MBAR_ARRIVE_EXPECT_TX(mb, 2048u);
            }
        }

        // ---- dual-row matvec: 32 cols, 4 independent f32x2 FMA chains ----
        const float* hp = &hs[cur][hbase];
        unsigned long long PA = 0ull, PB = 0ull, QA = 0ull, QB = 0ull;
#pragma unroll
        for (int k = 0; k < 8; k++) {
            ulonglong2 hv = *(const ulonglong2*)(hp + 4 * k);  // cols 4k..4k+3
            asm("fma.rn.f32x2 %0, %1, %2, %3;"
                : "=l"(PA) : "l"(wP[2 * k]),     "l"(hv.x), "l"(PA));
            asm("fma.rn.f32x2 %0, %1, %2, %3;"
                : "=l"(QA) : "l"(wQ[2 * k]),     "l"(hv.x), "l"(QA));
            asm("fma.rn.f32x2 %0, %1, %2, %3;"
                : "=l"(PB) : "l"(wP[2 * k + 1]), "l"(hv.y), "l"(PB));
            asm("fma.rn.f32x2 %0, %1, %2, %3;"
                : "=l"(QB) : "l"(wQ[2 * k + 1]), "l"(hv.y), "l"(QB));
        }
        unsigned long long SP, SQ;
        asm("add.rn.f32x2 %0, %1, %2;" : "=l"(SP) : "l"(PA), "l"(PB));
        asm("add.rn.f32x2 %0, %1, %2;" : "=l"(SQ) : "l"(QA), "l"(QB));
        uint32_t spx, spy, sqx, sqy;
        asm("mov.b64 {%0,%1}, %2;" : "=r"(spx), "=r"(spy) : "l"(SP));
        asm("mov.b64 {%0,%1}, %2;" : "=r"(sqx), "=r"(sqy) : "l"(SQ));
        // SP=(r0-even, r1-odd), SQ=(r1-even, r0-odd)
        float s0 = __uint_as_float(spx) + __uint_as_float(sqy);  // row r0
        float s1 = __uint_as_float(spy) + __uint_as_float(sqx);  // row r0+1

        // butterfly over the 16 lanes of my group (both chains independent)
        s0 += __shfl_xor_sync(0xffffffffu, s0, 1);
        s1 += __shfl_xor_sync(0xffffffffu, s1, 1);
        s0 += __shfl_xor_sync(0xffffffffu, s0, 2);
        s1 += __shfl_xor_sync(0xffffffffu, s1, 2);
        s0 += __shfl_xor_sync(0xffffffffu, s0, 4);
        s1 += __shfl_xor_sync(0xffffffffu, s1, 4);
        s0 += __shfl_xor_sync(0xffffffffu, s0, 8);
        s1 += __shfl_xor_sync(0xffffffffu, s1, 8);

        float z0 = s0 + xp0.x;
        float z1 = s1 + xp0.y;
        // fast accurate tanh: h = 1 - 2/(exp(2z)+1), via ex2/rcp MUFU
        float e0, e1, r0f, r1f;
        asm("ex2.approx.f32 %0, %1;" : "=f"(e0) : "f"(z0 * 2.885390082f));
        asm("ex2.approx.f32 %0, %1;" : "=f"(e1) : "f"(z1 * 2.885390082f));
        asm("rcp.approx.f32 %0, %1;" : "=f"(r0f) : "f"(e0 + 1.0f));
        asm("rcp.approx.f32 %0, %1;" : "=f"(r1f) : "f"(e1 + 1.0f));
        float h0 = fmaf(-2.0f, r0f, 1.0f);
        float h1 = fmaf(-2.0f, r1f, 1.0f);

        if (t + 1 < T_SEQ) {
            // one packed message: my 2 rows -> rank l's next-phase buffer
            unsigned long long pk;
            asm("mov.b64 %0, {%1,%2};" : "=l"(pk) : "f"(h0), "f"(h1));
            const uint32_t doff = cur ? doff0 : doff1;   // dest buf = cur^1
            const uint32_t moff = mbrel + (cur ? 0u : 8u);
            asm volatile(
                "st.async.weak.shared::cluster.mbarrier::complete_tx::bytes.b64 "
                "[%0], %1, [%2];"
                :: "r"(myrb + doff), "l"(pk), "r"(myrb + moff) : "memory");
        }
        if (l == 0)
            *(float2*)&out_h[(size_t)t * HID + r0] = make_float2(h0, h1);

        xp0 = xp1;
        xp1 = xpn;
    }
}

// ---------------------------------------------------------------------------
// Kernel 3: y = Wout @ concat(h_fwd[-1], h_rev[-1]) + bout   (unchanged)
// ---------------------------------------------------------------------------
__global__ void __launch_bounds__(256) readout_kernel(
    const float* __restrict__ Wout, const float* __restrict__ bout,
    float* __restrict__ out)
{
    const int j = blockIdx.x;
    const float* hf = out + 512 + (size_t)(T_SEQ - 1) * HID;
    const float* hr = out + 512 + (size_t)T_SEQ * HID + (size_t)(T_SEQ - 1) * HID;
    const float* wr = Wout + (size_t)j * (2 * HID);

    float s = 0.f;
    for (int i = threadIdx.x; i < HID; i += 256) s = fmaf(wr[i],       hf[i], s);
    for (int i = threadIdx.x; i < HID; i += 256) s = fmaf(wr[HID + i], hr[i], s);

#pragma unroll
    for (int o = 16; o > 0; o >>= 1) s += __shfl_xor_sync(0xffffffffu, s, o);

    __shared__ float red[8];
    if ((threadIdx.x & 31) == 0) red[threadIdx.x >> 5] = s;
    __syncthreads();
    if (threadIdx.x == 0) {
        float tot = 0.f;
#pragma unroll
        for (int i = 0; i < 8; i++) tot += red[i];
        out[j] = tot + bout[j];
    }
}

// ---------------------------------------------------------------------------
extern "C" void kernel_launch(void* const* d_in, const int* in_sizes, int n_in,
                              void* d_out, int out_size)
{
    const float* x    = (const float*)d_in[0];
    const float* Wx   = (const float*)d_in[1];
    const float* Wh   = (const float*)d_in[2];
    const float* b    = (const float*)d_in[3];
    const float* Wout = (const float*)d_in[4];
    const float* bout = (const float*)d_in[5];
    float* out = (float*)d_out;

    dim3 ggrid(HID / BN, T_SEQ / BM);           // (4, 256)
    gemm_xp_kernel<<<ggrid, 256>>>(x, Wx, b);

    // 2 clusters of 16 CTAs (nonportable cluster size)
    cudaFuncSetAttribute(scan_kernel,
                         cudaFuncAttributeNonPortableClusterSizeAllowed, 1);
    cudaLaunchConfig_t cfg = {};
    cfg.gridDim  = dim3(2 * CS, 1, 1);
    cfg.blockDim = dim3(NTHR, 1, 1);
    cfg.dynamicSmemBytes = 0;
    cfg.stream = 0;
    cudaLaunchAttribute attrs[1];
    attrs[0].id = cudaLaunchAttributeClusterDimension;
    attrs[0].val.clusterDim = {CS, 1, 1};
    cfg.attrs = attrs;
    cfg.numAttrs = 1;
    cudaLaunchKernelEx(&cfg, scan_kernel, Wh, out);

    readout_kernel<<<HID, 256>>>(Wout, bout, out);
}